// round 2
// baseline (speedup 1.0000x reference)
#include <cuda_runtime.h>
#include <math.h>

#define BATCH 4
#define CIN   256
#define HW    4096
#define DIM   64

typedef unsigned long long u64;

__device__ __forceinline__ u64 pack2(float lo, float hi) {
    u64 r; asm("mov.b64 %0, {%1, %2};" : "=l"(r) : "f"(lo), "f"(hi)); return r;
}
__device__ __forceinline__ float2 unpack2(u64 v) {
    float2 f; asm("mov.b64 {%0, %1}, %2;" : "=f"(f.x), "=f"(f.y) : "l"(v)); return f;
}
__device__ __forceinline__ u64 ffma2(u64 a, u64 b, u64 c) {
    u64 d; asm("fma.rn.f32x2 %0, %1, %2, %3;" : "=l"(d) : "l"(a), "l"(b), "l"(c)); return d;
}
__device__ __forceinline__ u64 fmul2(u64 a, u64 b) {
    u64 d; asm("mul.rn.f32x2 %0, %1, %2;" : "=l"(d) : "l"(a), "l"(b)); return d;
}

// Scratch: q, k, v, sa stored as [B][HW][D]
__device__ float g_q[BATCH * HW * DIM];
__device__ float g_k[BATCH * HW * DIM];
__device__ float g_v[BATCH * HW * DIM];
__device__ float g_sa[BATCH * HW * DIM];

// ---------------------------------------------------------------------------
// Kernel 1: QKV projections (f32x2).
// ---------------------------------------------------------------------------
__global__ __launch_bounds__(256) void qkv_kernel(
    const float* __restrict__ x,
    const float* __restrict__ wq, const float* __restrict__ bq,
    const float* __restrict__ wk, const float* __restrict__ bk,
    const float* __restrict__ wv, const float* __restrict__ bv)
{
    __shared__ u64   w_dup[64 * 64];  // [c_local][d], duplicated pairs
    __shared__ float x_s[64 * 64];    // [c_local][n_local]

    const int p  = blockIdx.z;
    const float* w    = (p == 0) ? wq : ((p == 1) ? wk : wv);
    const float* bias = (p == 0) ? bq : ((p == 1) ? bk : bv);
    float* out        = (p == 0) ? g_q : ((p == 1) ? g_k : g_v);

    const int b  = blockIdx.y;
    const int n0 = blockIdx.x * 64;
    const int tid = threadIdx.x;
    const int tx = tid & 15;
    const int ty = tid >> 4;

    u64 acc[4][2];
#pragma unroll
    for (int r = 0; r < 4; r++) { acc[r][0] = 0ull; acc[r][1] = 0ull; }

    for (int kc = 0; kc < 4; kc++) {
#pragma unroll
        for (int r = 0; r < 4; r++) {
            int row  = (tid >> 4) + r * 16;      // 0..63
            int col4 = (tid & 15) * 4;
            float4 wv4 = *(const float4*)&w[row * CIN + kc * 64 + col4];
            w_dup[(col4 + 0) * 64 + row] = pack2(wv4.x, wv4.x);
            w_dup[(col4 + 1) * 64 + row] = pack2(wv4.y, wv4.y);
            w_dup[(col4 + 2) * 64 + row] = pack2(wv4.z, wv4.z);
            w_dup[(col4 + 3) * 64 + row] = pack2(wv4.w, wv4.w);
            float4 xv4 = *(const float4*)&x[(b * CIN + kc * 64 + row) * HW + n0 + col4];
            *(float4*)&x_s[row * 64 + col4] = xv4;
        }
        __syncthreads();

#pragma unroll 16
        for (int kk = 0; kk < 64; kk++) {
            const u64* wr = &w_dup[kk * 64 + ty * 4];
            u64 w0 = wr[0], w1 = wr[1], w2 = wr[2], w3 = wr[3];
            ulonglong2 xb = *(const ulonglong2*)&x_s[kk * 64 + tx * 4];
            acc[0][0] = ffma2(w0, xb.x, acc[0][0]); acc[0][1] = ffma2(w0, xb.y, acc[0][1]);
            acc[1][0] = ffma2(w1, xb.x, acc[1][0]); acc[1][1] = ffma2(w1, xb.y, acc[1][1]);
            acc[2][0] = ffma2(w2, xb.x, acc[2][0]); acc[2][1] = ffma2(w2, xb.y, acc[2][1]);
            acc[3][0] = ffma2(w3, xb.x, acc[3][0]); acc[3][1] = ffma2(w3, xb.y, acc[3][1]);
        }
        __syncthreads();
    }

    float accf[4][4];
#pragma unroll
    for (int r = 0; r < 4; r++) {
        float2 a0 = unpack2(acc[r][0]);
        float2 a1 = unpack2(acc[r][1]);
        accf[r][0] = a0.x; accf[r][1] = a0.y; accf[r][2] = a1.x; accf[r][3] = a1.y;
    }
    float bias4[4];
#pragma unroll
    for (int r = 0; r < 4; r++) bias4[r] = bias[ty * 4 + r];

#pragma unroll
    for (int i = 0; i < 4; i++) {
        int n = n0 + tx * 4 + i;
        float4 o4;
        o4.x = accf[0][i] + bias4[0];
        o4.y = accf[1][i] + bias4[1];
        o4.z = accf[2][i] + bias4[2];
        o4.w = accf[3][i] + bias4[3];
        *(float4*)&out[(b * HW + n) * DIM + ty * 4] = o4;
    }
}

// ---------------------------------------------------------------------------
// Kernel 2: fused attention, f32x2 inner loops.
// smem: q_dup (u64 [d][i], 32KB) + k_t (float [d][j], 16KB) +
//       v_s (float [j][d], 16KB) + p_t (float [j][68], 17KB) = 82944 B
// ---------------------------------------------------------------------------
__global__ __launch_bounds__(256, 2) void attn_kernel()
{
    extern __shared__ char smraw[];
    u64*   q_dup = (u64*)smraw;                  // [64][64]
    float* k_t   = (float*)(smraw + 32768);      // [64][64] (d-major)
    float* v_s   = (float*)(smraw + 49152);      // [64][64] (j-major)
    float* p_t   = (float*)(smraw + 65536);      // [64][68] (j-major, padded)

    const int b  = blockIdx.y;
    const int i0 = blockIdx.x * 64;
    const int tid = threadIdx.x;
    const int tx = tid & 15;
    const int ty = tid >> 4;
    const int lj  = tid & 63;   // loader: distinct j/i per lane (conflict-free STS)
    const int ldq = tid >> 6;   // loader: d-quadrant

    // Load Q tile: q_dup[d][i] = (q,q) pairs. STS.64 banks = 2*lj -> 2-way max.
#pragma unroll
    for (int u = 0; u < 4; u++) {
        int d0 = ldq * 16 + u * 4;
        float4 q4 = *(const float4*)&g_q[(b * HW + i0 + lj) * DIM + d0];
        q_dup[(d0 + 0) * 64 + lj] = pack2(q4.x, q4.x);
        q_dup[(d0 + 1) * 64 + lj] = pack2(q4.y, q4.y);
        q_dup[(d0 + 2) * 64 + lj] = pack2(q4.z, q4.z);
        q_dup[(d0 + 3) * 64 + lj] = pack2(q4.w, q4.w);
    }

    u64 o[4][2];
    float m[4], l[4];
#pragma unroll
    for (int r = 0; r < 4; r++) {
        m[r] = -1e30f; l[r] = 0.0f; o[r][0] = 0ull; o[r][1] = 0ull;
    }

    // Prefetch K/V tile for jt = 0
    float4 kreg[4], vreg[4];
#pragma unroll
    for (int u = 0; u < 4; u++)
        kreg[u] = *(const float4*)&g_k[(b * HW + lj) * DIM + ldq * 16 + u * 4];
#pragma unroll
    for (int r = 0; r < 4; r++) {
        int row = (tid >> 4) + r * 16;
        vreg[r] = *(const float4*)&g_v[(b * HW + row) * DIM + tx * 4];
    }

    for (int jt = 0; jt < HW / 64; jt++) {
        __syncthreads();  // previous iteration's PV/softmax reads complete

        // Store K transposed (conflict-free: bank = lj mod 32) and V natural.
#pragma unroll
        for (int u = 0; u < 4; u++) {
            int d0 = ldq * 16 + u * 4;
            k_t[(d0 + 0) * 64 + lj] = kreg[u].x;
            k_t[(d0 + 1) * 64 + lj] = kreg[u].y;
            k_t[(d0 + 2) * 64 + lj] = kreg[u].z;
            k_t[(d0 + 3) * 64 + lj] = kreg[u].w;
        }
#pragma unroll
        for (int r = 0; r < 4; r++) {
            int row = (tid >> 4) + r * 16;
            *(float4*)&v_s[row * 64 + tx * 4] = vreg[r];
        }
        __syncthreads();

        // Prefetch next tile (hidden under ~2000 cyc of compute)
        if (jt + 1 < HW / 64) {
            int j0n = (jt + 1) * 64;
#pragma unroll
            for (int u = 0; u < 4; u++)
                kreg[u] = *(const float4*)&g_k[(b * HW + j0n + lj) * DIM + ldq * 16 + u * 4];
#pragma unroll
            for (int r = 0; r < 4; r++) {
                int row = (tid >> 4) + r * 16;
                vreg[r] = *(const float4*)&g_v[(b * HW + j0n + row) * DIM + tx * 4];
            }
        }

        // S = Q^T K, packed pairs along j
        u64 s[4][2];
#pragma unroll
        for (int r = 0; r < 4; r++) { s[r][0] = 0ull; s[r][1] = 0ull; }

#pragma unroll 16
        for (int d = 0; d < 64; d++) {
            const u64* qr = &q_dup[d * 64 + ty * 4];
            u64 q0 = qr[0], q1 = qr[1], q2 = qr[2], q3 = qr[3];
            ulonglong2 ka = *(const ulonglong2*)&k_t[d * 64 + tx * 4];
            s[0][0] = ffma2(q0, ka.x, s[0][0]); s[0][1] = ffma2(q0, ka.y, s[0][1]);
            s[1][0] = ffma2(q1, ka.x, s[1][0]); s[1][1] = ffma2(q1, ka.y, s[1][1]);
            s[2][0] = ffma2(q2, ka.x, s[2][0]); s[2][1] = ffma2(q2, ka.y, s[2][1]);
            s[3][0] = ffma2(q3, ka.x, s[3][0]); s[3][1] = ffma2(q3, ka.y, s[3][1]);
        }

        // online softmax
#pragma unroll
        for (int r = 0; r < 4; r++) {
            float2 sa = unpack2(s[r][0]);
            float2 sb = unpack2(s[r][1]);
            float rm = fmaxf(fmaxf(sa.x, sa.y), fmaxf(sb.x, sb.y));
            rm = fmaxf(rm, __shfl_xor_sync(0xffffffffu, rm, 8));
            rm = fmaxf(rm, __shfl_xor_sync(0xffffffffu, rm, 4));
            rm = fmaxf(rm, __shfl_xor_sync(0xffffffffu, rm, 2));
            rm = fmaxf(rm, __shfl_xor_sync(0xffffffffu, rm, 1));
            float mn = fmaxf(m[r], rm);
            float alpha = __expf(m[r] - mn);
            float p0 = __expf(sa.x - mn);
            float p1 = __expf(sa.y - mn);
            float p2 = __expf(sb.x - mn);
            float p3 = __expf(sb.y - mn);
            float rs = (p0 + p1) + (p2 + p3);
            rs += __shfl_xor_sync(0xffffffffu, rs, 8);
            rs += __shfl_xor_sync(0xffffffffu, rs, 4);
            rs += __shfl_xor_sync(0xffffffffu, rs, 2);
            rs += __shfl_xor_sync(0xffffffffu, rs, 1);
            l[r] = l[r] * alpha + rs;
            m[r] = mn;
            u64 al = pack2(alpha, alpha);
            o[r][0] = fmul2(o[r][0], al);
            o[r][1] = fmul2(o[r][1], al);
            // p_t[j][i] (stride 68)
            p_t[(tx * 4 + 0) * 68 + ty * 4 + r] = p0;
            p_t[(tx * 4 + 1) * 68 + ty * 4 + r] = p1;
            p_t[(tx * 4 + 2) * 68 + ty * 4 + r] = p2;
            p_t[(tx * 4 + 3) * 68 + ty * 4 + r] = p3;
        }
        __syncthreads();

        // O += P * V, packed pairs along d
#pragma unroll 16
        for (int j = 0; j < 64; j++) {
            float4 pf = *(const float4*)&p_t[j * 68 + ty * 4];  // broadcast
            ulonglong2 va = *(const ulonglong2*)&v_s[j * 64 + tx * 4];
            u64 pd0 = pack2(pf.x, pf.x);
            u64 pd1 = pack2(pf.y, pf.y);
            u64 pd2 = pack2(pf.z, pf.z);
            u64 pd3 = pack2(pf.w, pf.w);
            o[0][0] = ffma2(pd0, va.x, o[0][0]); o[0][1] = ffma2(pd0, va.y, o[0][1]);
            o[1][0] = ffma2(pd1, va.x, o[1][0]); o[1][1] = ffma2(pd1, va.y, o[1][1]);
            o[2][0] = ffma2(pd2, va.x, o[2][0]); o[2][1] = ffma2(pd2, va.y, o[2][1]);
            o[3][0] = ffma2(pd3, va.x, o[3][0]); o[3][1] = ffma2(pd3, va.y, o[3][1]);
        }
    }

    // normalize + store sa as [n][d]
#pragma unroll
    for (int r = 0; r < 4; r++) {
        float inv = 1.0f / l[r];
        u64 iv = pack2(inv, inv);
        o[r][0] = fmul2(o[r][0], iv);
        o[r][1] = fmul2(o[r][1], iv);
        float2 oa = unpack2(o[r][0]);
        float2 ob = unpack2(o[r][1]);
        int i = i0 + ty * 4 + r;
        *(float4*)&g_sa[(b * HW + i) * DIM + tx * 4] = make_float4(oa.x, oa.y, ob.x, ob.y);
    }
}

// ---------------------------------------------------------------------------
// Kernel 3: output projection + gamma * out + residual (f32x2).
// ---------------------------------------------------------------------------
__global__ __launch_bounds__(256) void proj_kernel(
    const float* __restrict__ x,
    const float* __restrict__ wsa,
    const float* __restrict__ bsa,
    const float* __restrict__ gamma,
    float* __restrict__ out)
{
    __shared__ u64   wsa_dup[64 * 64];  // [d][c_local], duplicated pairs
    __shared__ float sa_t[64 * 64];     // [d][n_local]

    const int b  = blockIdx.z;
    const int cc = blockIdx.y;
    const int n0 = blockIdx.x * 64;
    const int tid = threadIdx.x;
    const int tx = tid & 15;
    const int ty = tid >> 4;

#pragma unroll
    for (int r = 0; r < 4; r++) {
        int row = (tid >> 4) + r * 16;
        int d4  = (tid & 15) * 4;
        float4 w4 = *(const float4*)&wsa[(cc * 64 + row) * DIM + d4];
        wsa_dup[(d4 + 0) * 64 + row] = pack2(w4.x, w4.x);
        wsa_dup[(d4 + 1) * 64 + row] = pack2(w4.y, w4.y);
        wsa_dup[(d4 + 2) * 64 + row] = pack2(w4.z, w4.z);
        wsa_dup[(d4 + 3) * 64 + row] = pack2(w4.w, w4.w);
        float4 s4 = *(const float4*)&g_sa[(b * HW + n0 + row) * DIM + d4];
        sa_t[(d4 + 0) * 64 + row] = s4.x;
        sa_t[(d4 + 1) * 64 + row] = s4.y;
        sa_t[(d4 + 2) * 64 + row] = s4.z;
        sa_t[(d4 + 3) * 64 + row] = s4.w;
    }
    __syncthreads();

    u64 acc[4][2];
#pragma unroll
    for (int r = 0; r < 4; r++) { acc[r][0] = 0ull; acc[r][1] = 0ull; }

#pragma unroll 16
    for (int d = 0; d < 64; d++) {
        const u64* wr = &wsa_dup[d * 64 + ty * 4];
        u64 w0 = wr[0], w1 = wr[1], w2 = wr[2], w3 = wr[3];
        ulonglong2 sb = *(const ulonglong2*)&sa_t[d * 64 + tx * 4];
        acc[0][0] = ffma2(w0, sb.x, acc[0][0]); acc[0][1] = ffma2(w0, sb.y, acc[0][1]);
        acc[1][0] = ffma2(w1, sb.x, acc[1][0]); acc[1][1] = ffma2(w1, sb.y, acc[1][1]);
        acc[2][0] = ffma2(w2, sb.x, acc[2][0]); acc[2][1] = ffma2(w2, sb.y, acc[2][1]);
        acc[3][0] = ffma2(w3, sb.x, acc[3][0]); acc[3][1] = ffma2(w3, sb.y, acc[3][1]);
    }

    const float g = gamma[0];
#pragma unroll
    for (int r = 0; r < 4; r++) {
        float2 a0 = unpack2(acc[r][0]);
        float2 a1 = unpack2(acc[r][1]);
        float af[4] = {a0.x, a0.y, a1.x, a1.y};
        int c = cc * 64 + ty * 4 + r;
        float bias = bsa[c];
        int base = (b * CIN + c) * HW + n0 + tx * 4;
        float4 xv = *(const float4*)&x[base];
        float4 o4;
        o4.x = g * (af[0] + bias) + xv.x;
        o4.y = g * (af[1] + bias) + xv.y;
        o4.z = g * (af[2] + bias) + xv.z;
        o4.w = g * (af[3] + bias) + xv.w;
        *(float4*)&out[base] = o4;
    }
}

// ---------------------------------------------------------------------------
extern "C" void kernel_launch(void* const* d_in, const int* in_sizes, int n_in,
                              void* d_out, int out_size)
{
    const float* x     = (const float*)d_in[0];
    const float* wq    = (const float*)d_in[1];
    const float* bq    = (const float*)d_in[2];
    const float* wk    = (const float*)d_in[3];
    const float* bk    = (const float*)d_in[4];
    const float* wv    = (const float*)d_in[5];
    const float* bv    = (const float*)d_in[6];
    const float* wsa   = (const float*)d_in[7];
    const float* bsa   = (const float*)d_in[8];
    const float* gamma = (const float*)d_in[9];
    float* out = (float*)d_out;

    cudaFuncSetAttribute(attn_kernel, cudaFuncAttributeMaxDynamicSharedMemorySize, 82944);

    qkv_kernel<<<dim3(HW / 64, BATCH, 3), 256>>>(x, wq, bq, wk, bk, wv, bv);
    attn_kernel<<<dim3(HW / 64, BATCH), 256, 82944>>>();
    proj_kernel<<<dim3(HW / 64, CIN / 64, BATCH), 256>>>(x, wsa, bsa, gamma, out);
}

// round 4
// speedup vs baseline: 3.4161x; 3.4161x over previous
#include <cuda_runtime.h>
#include <cuda_bf16.h>
#include <math.h>
#include <stdint.h>
#include <string.h>

#define BATCH 4
#define CIN   256
#define HW    4096
#define DIM   64

typedef unsigned int u32;
typedef unsigned long long u64;

// ---------------------------------------------------------------------------
// Device scratch
// ---------------------------------------------------------------------------
__device__ __nv_bfloat16 g_qh[BATCH * HW * DIM];
__device__ __nv_bfloat16 g_ql[BATCH * HW * DIM];
__device__ __nv_bfloat16 g_kh[BATCH * HW * DIM];
__device__ __nv_bfloat16 g_kl[BATCH * HW * DIM];
__device__ __nv_bfloat16 g_vth[BATCH * DIM * HW];  // transposed [b][d][j]
__device__ __nv_bfloat16 g_vtl[BATCH * DIM * HW];
__device__ float g_sa[BATCH * HW * DIM];

// ---------------------------------------------------------------------------
// Helpers
// ---------------------------------------------------------------------------
__device__ __forceinline__ uint32_t smem_u32(const void* p) {
    uint32_t a;
    asm("{ .reg .u64 t; cvta.to.shared.u64 t, %1; cvt.u32.u64 %0, t; }" : "=r"(a) : "l"(p));
    return a;
}
// pack two floats into bf16x2: lo -> bits[15:0], hi -> bits[31:16]
__device__ __forceinline__ u32 packbf(float lo, float hi) {
    u32 r;
    asm("cvt.rn.bf16x2.f32 %0, %1, %2;" : "=r"(r) : "f"(hi), "f"(lo));
    return r;
}
__device__ __forceinline__ float2 unpackbf(u32 u) {
    __nv_bfloat162 h;
    memcpy(&h, &u, 4);
    return make_float2(__bfloat162float(h.x), __bfloat162float(h.y));
}

__device__ __forceinline__ void mma16816(float* c, const u32* a, const u32* b) {
    asm volatile(
        "mma.sync.aligned.m16n8k16.row.col.f32.bf16.bf16.f32 "
        "{%0,%1,%2,%3}, {%4,%5,%6,%7}, {%8,%9}, {%0,%1,%2,%3};"
        : "+f"(c[0]), "+f"(c[1]), "+f"(c[2]), "+f"(c[3])
        : "r"(a[0]), "r"(a[1]), "r"(a[2]), "r"(a[3]), "r"(b[0]), "r"(b[1]));
}
__device__ __forceinline__ void ldsm4(u32* r, uint32_t addr) {
    asm volatile("ldmatrix.sync.aligned.m8n8.x4.shared.b16 {%0,%1,%2,%3}, [%4];"
        : "=r"(r[0]), "=r"(r[1]), "=r"(r[2]), "=r"(r[3]) : "r"(addr));
}
__device__ __forceinline__ void ldsm2(u32* r, uint32_t addr) {
    asm volatile("ldmatrix.sync.aligned.m8n8.x2.shared.b16 {%0,%1}, [%2];"
        : "=r"(r[0]), "=r"(r[1]) : "r"(addr));
}
#define CP16(dst, src) asm volatile("cp.async.cg.shared.global [%0], [%1], 16;" :: "r"(dst), "l"(src))
#define CPC()  asm volatile("cp.async.commit_group;")
#define CPW0() asm volatile("cp.async.wait_group 0;")

// XOR swizzle: 128B rows (8 x 16B granules), 256B rows (16 granules)
__device__ __forceinline__ u32 swz128(u32 row, u32 g) { return row * 128u + ((g ^ (row & 7u)) << 4); }
__device__ __forceinline__ u32 swz256(u32 row, u32 g) { return row * 256u + ((g ^ (row & 7u)) << 4); }

// ---------------------------------------------------------------------------
// Kernel 1: QKV projections (fp32 SIMT) + bf16 hi/lo epilogue.
// ---------------------------------------------------------------------------
__global__ __launch_bounds__(256) void qkv_kernel(
    const float* __restrict__ x,
    const float* __restrict__ wq, const float* __restrict__ bq,
    const float* __restrict__ wk, const float* __restrict__ bk,
    const float* __restrict__ wv, const float* __restrict__ bv)
{
    __shared__ float w_t[64 * 64];
    __shared__ float x_s[64 * 64];

    const int p  = blockIdx.z;
    const float* w    = (p == 0) ? wq : ((p == 1) ? wk : wv);
    const float* bias = (p == 0) ? bq : ((p == 1) ? bk : bv);

    const int b  = blockIdx.y;
    const int n0 = blockIdx.x * 64;
    const int tid = threadIdx.x;
    const int tx = tid & 15;
    const int ty = tid >> 4;

    float acc[4][4];
#pragma unroll
    for (int r = 0; r < 4; r++)
#pragma unroll
        for (int c = 0; c < 4; c++) acc[r][c] = 0.0f;

    for (int kc = 0; kc < 4; kc++) {
#pragma unroll
        for (int r = 0; r < 4; r++) {
            int row  = (tid >> 4) + r * 16;
            int col4 = (tid & 15) * 4;
            float4 wv4 = *(const float4*)&w[row * CIN + kc * 64 + col4];
            w_t[(col4 + 0) * 64 + row] = wv4.x;
            w_t[(col4 + 1) * 64 + row] = wv4.y;
            w_t[(col4 + 2) * 64 + row] = wv4.z;
            w_t[(col4 + 3) * 64 + row] = wv4.w;
            float4 xv4 = *(const float4*)&x[(b * CIN + kc * 64 + row) * HW + n0 + col4];
            *(float4*)&x_s[row * 64 + col4] = xv4;
        }
        __syncthreads();

#pragma unroll 16
        for (int kk = 0; kk < 64; kk++) {
            float4 a4 = *(const float4*)&w_t[kk * 64 + ty * 4];
            float4 b4 = *(const float4*)&x_s[kk * 64 + tx * 4];
            float ar[4] = {a4.x, a4.y, a4.z, a4.w};
            float br[4] = {b4.x, b4.y, b4.z, b4.w};
#pragma unroll
            for (int r = 0; r < 4; r++)
#pragma unroll
                for (int c = 0; c < 4; c++) acc[r][c] += ar[r] * br[c];
        }
        __syncthreads();
    }

    float bias4[4];
#pragma unroll
    for (int r = 0; r < 4; r++) bias4[r] = bias[ty * 4 + r];

    if (p < 2) {
        __nv_bfloat16* oh = (p == 0) ? g_qh : g_kh;
        __nv_bfloat16* ol = (p == 0) ? g_ql : g_kl;
#pragma unroll
        for (int i = 0; i < 4; i++) {
            int n = n0 + tx * 4 + i;
            float v0 = acc[0][i] + bias4[0];
            float v1 = acc[1][i] + bias4[1];
            float v2 = acc[2][i] + bias4[2];
            float v3 = acc[3][i] + bias4[3];
            u32 h01 = packbf(v0, v1), h23 = packbf(v2, v3);
            float2 f01 = unpackbf(h01), f23 = unpackbf(h23);
            u32 l01 = packbf(v0 - f01.x, v1 - f01.y);
            u32 l23 = packbf(v2 - f23.x, v3 - f23.y);
            size_t off = (size_t)(b * HW + n) * DIM + ty * 4;
            *(uint2*)&oh[off] = make_uint2(h01, h23);
            *(uint2*)&ol[off] = make_uint2(l01, l23);
        }
    } else {
#pragma unroll
        for (int r = 0; r < 4; r++) {
            int d = ty * 4 + r;
            float v0 = acc[r][0] + bias4[r];
            float v1 = acc[r][1] + bias4[r];
            float v2 = acc[r][2] + bias4[r];
            float v3 = acc[r][3] + bias4[r];
            u32 h01 = packbf(v0, v1), h23 = packbf(v2, v3);
            float2 f01 = unpackbf(h01), f23 = unpackbf(h23);
            u32 l01 = packbf(v0 - f01.x, v1 - f01.y);
            u32 l23 = packbf(v2 - f23.x, v3 - f23.y);
            size_t off = (size_t)(b * DIM + d) * HW + n0 + tx * 4;
            *(uint2*)&g_vth[off] = make_uint2(h01, h23);
            *(uint2*)&g_vtl[off] = make_uint2(l01, l23);
        }
    }
}

// ---------------------------------------------------------------------------
// Kernel 2: HMMA flash attention (bf16 hi/lo, no max subtraction).
// 256 threads = 8 warps (4 M-groups x 2 j-halves). BM=128, BN=128.
// Smem: Qh 0 (16K) | Ql 16K | buf0 32K..96K | buf1 96K..160K
//       buf: Kh +0, Kl +16K, Vh +32K, Vl +48K  (K: 128x128B sw, V: 64x256B sw)
// Epilogue reuse: O0 @0 (32K), O1 @32K, l @64K.
// ---------------------------------------------------------------------------
#define SM_TOTAL 163840

__device__ __forceinline__ void load_kv(u32 sb, u32 bufbase, int b, int j0, int tid)
{
    const char* kh = (const char*)&g_kh[(size_t)(b * HW + j0) * DIM];
    const char* kl = (const char*)&g_kl[(size_t)(b * HW + j0) * DIM];
#pragma unroll
    for (int i = 0; i < 4; i++) {
        int id = tid + i * 256, row = id >> 3, g = id & 7;
        u32 o = swz128(row, g);
        u32 so = row * 128 + g * 16;
        CP16(sb + bufbase + o, kh + so);
        CP16(sb + bufbase + 16384 + o, kl + so);
    }
    const char* vh = (const char*)&g_vth[(size_t)b * DIM * HW + j0];
    const char* vl = (const char*)&g_vtl[(size_t)b * DIM * HW + j0];
#pragma unroll
    for (int i = 0; i < 4; i++) {
        int id = tid + i * 256, d = id >> 4, g = id & 15;
        u32 o = swz256(d, g);
        u32 so = d * (HW * 2) + g * 16;
        CP16(sb + bufbase + 32768 + o, vh + so);
        CP16(sb + bufbase + 49152 + o, vl + so);
    }
}

__global__ __launch_bounds__(256, 1) void attn_kernel()
{
    extern __shared__ char sm[];
    const u32 sb = smem_u32(sm);
    const int tid  = threadIdx.x;
    const int lane = tid & 31;
    const int wid  = tid >> 5;
    const int wm = wid & 3;      // M group: rows wm*32 .. +31
    const int wn = wid >> 2;     // j half:  cols wn*64 .. +63
    const int b  = blockIdx.y;
    const int i0 = blockIdx.x * 128;
    const int g  = lane >> 2;    // group id 0..7
    const int t  = lane & 3;     // thread-in-group

    // prologue: load Q (hi/lo) and KV tile 0
    {
        const char* qh = (const char*)&g_qh[(size_t)(b * HW + i0) * DIM];
        const char* ql = (const char*)&g_ql[(size_t)(b * HW + i0) * DIM];
#pragma unroll
        for (int i = 0; i < 4; i++) {
            int id = tid + i * 256, row = id >> 3, gg = id & 7;
            u32 o = swz128(row, gg);
            u32 so = row * 128 + gg * 16;
            CP16(sb + 0 + o, qh + so);
            CP16(sb + 16384 + o, ql + so);
        }
        load_kv(sb, 32768, b, 0, tid);
        CPC();
    }

    float oc[2][8][4];
    float lsum[2][2];
#pragma unroll
    for (int mt = 0; mt < 2; mt++) {
        lsum[mt][0] = 0.0f; lsum[mt][1] = 0.0f;
#pragma unroll
        for (int dnt = 0; dnt < 8; dnt++)
#pragma unroll
            for (int e = 0; e < 4; e++) oc[mt][dnt][e] = 0.0f;
    }

    // Precomputed per-lane address components
    const u32 q_row = wm * 32 + (lane & 15);       // + mt*16
    const u32 q_gsel = (u32)(lane >> 4);           // + kt*2
    const u32 k_row = wn * 64 + (lane & 7);        // + nt*8
    const u32 k_gsel = (u32)((lane >> 3) & 1);     // + kt*2
    const u32 v_row = (u32)(lane & 7);             // + dnt*8
    const u32 v_gsel = wn * 8 + ((lane >> 3) & 1); // + jkt*2

    for (int jt = 0; jt < HW / 128; jt++) {
        CPW0();
        __syncthreads();
        const u32 buf = 32768 + (u32)(jt & 1) * 65536;
        if (jt + 1 < HW / 128)
            load_kv(sb, 32768 + (u32)((jt + 1) & 1) * 65536, b, (jt + 1) * 128, tid);
        CPC();

        // ---- S = Q K^T (hi/lo, 3 products) ----
        float sc[2][8][4];
#pragma unroll
        for (int mt = 0; mt < 2; mt++)
#pragma unroll
            for (int nt = 0; nt < 8; nt++)
#pragma unroll
                for (int e = 0; e < 4; e++) sc[mt][nt][e] = 0.0f;

#pragma unroll
        for (int kt = 0; kt < 4; kt++) {
            u32 aqh[2][4], aql[2][4];
#pragma unroll
            for (int mt = 0; mt < 2; mt++) {
                u32 ro = q_row + mt * 16;
                u32 gg = q_gsel + kt * 2;
                ldsm4(aqh[mt], sb + 0 + swz128(ro, gg));
                ldsm4(aql[mt], sb + 16384 + swz128(ro, gg));
            }
#pragma unroll
            for (int nt = 0; nt < 8; nt++) {
                u32 bh[2], bl[2];
                u32 ro = k_row + nt * 8;
                u32 gg = k_gsel + kt * 2;
                ldsm2(bh, sb + buf + swz128(ro, gg));
                ldsm2(bl, sb + buf + 16384 + swz128(ro, gg));
#pragma unroll
                for (int mt = 0; mt < 2; mt++) {
                    mma16816(sc[mt][nt], aqh[mt], bh);
                    mma16816(sc[mt][nt], aqh[mt], bl);
                    mma16816(sc[mt][nt], aql[mt], bh);
                }
            }
        }

        // ---- softmax (unnormalized) + PV, per 16-j chunk ----
#pragma unroll
        for (int jkt = 0; jkt < 4; jkt++) {
            u32 ph[2][4], pl[2][4];
#pragma unroll
            for (int mt = 0; mt < 2; mt++) {
#pragma unroll
                for (int h = 0; h < 2; h++) {
                    int nt = jkt * 2 + h;
                    float e0 = __expf(sc[mt][nt][0]);
                    float e1 = __expf(sc[mt][nt][1]);
                    float e2 = __expf(sc[mt][nt][2]);
                    float e3 = __expf(sc[mt][nt][3]);
                    lsum[mt][0] += e0 + e1;
                    lsum[mt][1] += e2 + e3;
                    u32 h01 = packbf(e0, e1);
                    u32 h23 = packbf(e2, e3);
                    ph[mt][h * 2 + 0] = h01;
                    ph[mt][h * 2 + 1] = h23;
                    float r0 = e0 - __uint_as_float(h01 << 16);
                    float r1 = e1 - __uint_as_float(h01 & 0xFFFF0000u);
                    float r2 = e2 - __uint_as_float(h23 << 16);
                    float r3 = e3 - __uint_as_float(h23 & 0xFFFF0000u);
                    pl[mt][h * 2 + 0] = packbf(r0, r1);
                    pl[mt][h * 2 + 1] = packbf(r2, r3);
                }
            }
#pragma unroll
            for (int dnt = 0; dnt < 8; dnt++) {
                u32 bvh[2], bvl[2];
                u32 ro = v_row + dnt * 8;
                u32 gg = v_gsel + jkt * 2;
                ldsm2(bvh, sb + buf + 32768 + swz256(ro, gg));
                ldsm2(bvl, sb + buf + 49152 + swz256(ro, gg));
#pragma unroll
                for (int mt = 0; mt < 2; mt++) {
                    mma16816(oc[mt][dnt], ph[mt], bvh);
                    mma16816(oc[mt][dnt], ph[mt], bvl);
                    mma16816(oc[mt][dnt], pl[mt], bvh);
                }
            }
        }
        __syncthreads();
    }

    // ---- epilogue: combine j-half partials, normalize, store ----
    // row-sum reduce over t lanes
    float* lp = (float*)(sm + 65536);   // [wn][128]
#pragma unroll
    for (int mt = 0; mt < 2; mt++)
#pragma unroll
        for (int r = 0; r < 2; r++) {
            float v = lsum[mt][r];
            v += __shfl_xor_sync(0xffffffffu, v, 1);
            v += __shfl_xor_sync(0xffffffffu, v, 2);
            if (t == 0) lp[wn * 128 + wm * 32 + mt * 16 + r * 8 + g] = v;
        }
    // O partials
    float* op = (float*)(sm + wn * 32768);
#pragma unroll
    for (int mt = 0; mt < 2; mt++)
#pragma unroll
        for (int dnt = 0; dnt < 8; dnt++) {
            int r0 = wm * 32 + mt * 16 + g;
            int c = dnt * 8 + t * 2;
            *(float2*)&op[r0 * 64 + c]       = make_float2(oc[mt][dnt][0], oc[mt][dnt][1]);
            *(float2*)&op[(r0 + 8) * 64 + c] = make_float2(oc[mt][dnt][2], oc[mt][dnt][3]);
        }
    __syncthreads();

    float* o0 = (float*)sm;
    float* o1 = (float*)(sm + 32768);
    float* lpf = (float*)(sm + 65536);
#pragma unroll
    for (int i = 0; i < 8; i++) {
        int idx = tid + i * 256;       // 0..2047
        int row = idx >> 4, c4 = (idx & 15) * 4;
        float invl = 1.0f / (lpf[row] + lpf[128 + row]);
        float4 a = *(float4*)&o0[row * 64 + c4];
        float4 bb = *(float4*)&o1[row * 64 + c4];
        float4 o;
        o.x = (a.x + bb.x) * invl;
        o.y = (a.y + bb.y) * invl;
        o.z = (a.z + bb.z) * invl;
        o.w = (a.w + bb.w) * invl;
        *(float4*)&g_sa[(size_t)(b * HW + i0 + row) * DIM + c4] = o;
    }
}

// ---------------------------------------------------------------------------
// Kernel 3: output projection + gamma * out + residual (fp32).
// ---------------------------------------------------------------------------
__global__ __launch_bounds__(256) void proj_kernel(
    const float* __restrict__ x,
    const float* __restrict__ wsa,
    const float* __restrict__ bsa,
    const float* __restrict__ gamma,
    float* __restrict__ out)
{
    __shared__ float wsa_t[64 * 64];
    __shared__ float sa_t[64 * 64];

    const int b  = blockIdx.z;
    const int cc = blockIdx.y;
    const int n0 = blockIdx.x * 64;
    const int tid = threadIdx.x;
    const int tx = tid & 15;
    const int ty = tid >> 4;

#pragma unroll
    for (int r = 0; r < 4; r++) {
        int row = (tid >> 4) + r * 16;
        int d4  = (tid & 15) * 4;
        float4 w4 = *(const float4*)&wsa[(cc * 64 + row) * DIM + d4];
        wsa_t[(d4 + 0) * 64 + row] = w4.x;
        wsa_t[(d4 + 1) * 64 + row] = w4.y;
        wsa_t[(d4 + 2) * 64 + row] = w4.z;
        wsa_t[(d4 + 3) * 64 + row] = w4.w;
        float4 s4 = *(const float4*)&g_sa[(size_t)(b * HW + n0 + row) * DIM + d4];
        sa_t[(d4 + 0) * 64 + row] = s4.x;
        sa_t[(d4 + 1) * 64 + row] = s4.y;
        sa_t[(d4 + 2) * 64 + row] = s4.z;
        sa_t[(d4 + 3) * 64 + row] = s4.w;
    }
    __syncthreads();

    float acc[4][4];
#pragma unroll
    for (int r = 0; r < 4; r++)
#pragma unroll
        for (int c = 0; c < 4; c++) acc[r][c] = 0.0f;

#pragma unroll 16
    for (int d = 0; d < 64; d++) {
        float4 a4 = *(const float4*)&wsa_t[d * 64 + ty * 4];
        float4 b4 = *(const float4*)&sa_t[d * 64 + tx * 4];
        float ar[4] = {a4.x, a4.y, a4.z, a4.w};
        float br[4] = {b4.x, b4.y, b4.z, b4.w};
#pragma unroll
        for (int r = 0; r < 4; r++)
#pragma unroll
            for (int c = 0; c < 4; c++) acc[r][c] += ar[r] * br[c];
    }

    const float gm = gamma[0];
#pragma unroll
    for (int r = 0; r < 4; r++) {
        int c = cc * 64 + ty * 4 + r;
        float bias = bsa[c];
        int base = (b * CIN + c) * HW + n0 + tx * 4;
        float4 xv = *(const float4*)&x[base];
        float4 o4;
        o4.x = gm * (acc[r][0] + bias) + xv.x;
        o4.y = gm * (acc[r][1] + bias) + xv.y;
        o4.z = gm * (acc[r][2] + bias) + xv.z;
        o4.w = gm * (acc[r][3] + bias) + xv.w;
        *(float4*)&out[base] = o4;
    }
}

// ---------------------------------------------------------------------------
extern "C" void kernel_launch(void* const* d_in, const int* in_sizes, int n_in,
                              void* d_out, int out_size)
{
    const float* x     = (const float*)d_in[0];
    const float* wq    = (const float*)d_in[1];
    const float* bq    = (const float*)d_in[2];
    const float* wk    = (const float*)d_in[3];
    const float* bk    = (const float*)d_in[4];
    const float* wv    = (const float*)d_in[5];
    const float* bv    = (const float*)d_in[6];
    const float* wsa   = (const float*)d_in[7];
    const float* bsa   = (const float*)d_in[8];
    const float* gamma = (const float*)d_in[9];
    float* out = (float*)d_out;

    cudaFuncSetAttribute(attn_kernel, cudaFuncAttributeMaxDynamicSharedMemorySize, SM_TOTAL);

    qkv_kernel<<<dim3(HW / 64, BATCH, 3), 256>>>(x, wq, bq, wk, bk, wv, bv);
    attn_kernel<<<dim3(HW / 128, BATCH), 256, SM_TOTAL>>>();
    proj_kernel<<<dim3(HW / 64, CIN / 64, BATCH), 256>>>(x, wsa, bsa, gamma, out);
}